// round 12
// baseline (speedup 1.0000x reference)
#include <cuda_runtime.h>
#include <cuda_fp16.h>
#include <math.h>
#include <stdint.h>

#define LSEQ   2048
#define DMODEL 512
#define NLAYER 8
#define DSTATE 16
#define DCONV  4
#define DINNER 1024
#define DTRANK 32
#define VOCAB  4096
#define XDIM   64   // DT_RANK + 2*D_STATE

// ---------------- scratch (static device globals; no allocation) ----------------
__device__ float g_h[LSEQ * DMODEL];
__device__ float g_xz[LSEQ * 2 * DINNER];
__device__ float g_u[LSEQ * DINNER];
__device__ float g_uT[DINNER * LSEQ];
__device__ float g_xpart[4 * LSEQ * XDIM];
__device__ float g_bcT[2 * DSTATE * LSEQ];  // B rows [0..15], C rows [16..31], transposed
__device__ float g_deltaT[DINNER * LSEQ];
__device__ float g_loss[2];

// fp16 buffers
__device__ __half g_a16[LSEQ * DINNER];
__device__ __half g_wemb16[VOCAB * DMODEL];
__device__ __half g_win16[NLAYER * 2 * DINNER * DMODEL];
__device__ __half g_wout16[NLAYER * DMODEL * DINNER];

// =============================== PTX helpers ===============================
__device__ __forceinline__ uint32_t smem_to_u32(const void* p) {
    uint32_t a;
    asm("{ .reg .u64 t; cvta.to.shared.u64 t, %1; cvt.u32.u64 %0, t; }"
        : "=r"(a) : "l"(p));
    return a;
}

#define MBARRIER_INIT(mbar, cnt) \
    asm volatile("mbarrier.init.shared.b64 [%0], %1;" \
        :: "r"((uint32_t)(mbar)), "r"((uint32_t)(cnt)) : "memory")

#define MBARRIER_ARRIVE(mbar) \
    asm volatile("mbarrier.arrive.shared.b64 _, [%0];" \
        :: "r"((uint32_t)(mbar)) : "memory")

#define MBARRIER_ARRIVE_EXPECT_TX(mbar, bytes) \
    asm volatile("mbarrier.arrive.expect_tx.shared.b64 _, [%0], %1;" \
        :: "r"((uint32_t)(mbar)), "r"((uint32_t)(bytes)) : "memory")

#define MBARRIER_WAIT_PARITY(mbar, parity) do { \
    uint32_t _m = (uint32_t)(mbar); \
    uint32_t _p = (uint32_t)(parity); \
    uint32_t _done; \
    asm volatile("{\n\t.reg .pred p;\n\t" \
        "mbarrier.try_wait.parity.acquire.cta.shared::cta.b64 p, [%1], %2;\n\t" \
        "selp.b32 %0, 1, 0, p;\n\t}" : "=r"(_done) : "r"(_m), "r"(_p) : "memory"); \
    if (!_done) { \
        asm volatile("{\n\t.reg .pred P1;\n\t" \
            "WAIT_LOOP_%=:\n\t" \
            "mbarrier.try_wait.parity.acquire.cta.shared::cta.b64 P1, [%0], %1, 0x989680;\n\t" \
            "@P1 bra.uni WAIT_DONE_%=;\n\t" \
            "bra.uni WAIT_LOOP_%=;\n\t" \
            "WAIT_DONE_%=:\n\t}" :: "r"(_m), "r"(_p) : "memory"); \
    } \
} while (0)

#define CP_BULK(dst, src, size, mbar) \
    asm volatile("cp.async.bulk.shared::cta.global.mbarrier::complete_tx::bytes " \
        "[%0], [%1], %2, [%3];" \
        :: "r"((uint32_t)(dst)), "l"(src), "r"((uint32_t)(size)), \
           "r"((uint32_t)(mbar)) : "memory")

__device__ __forceinline__ void ldmatrix_x4(uint32_t* r, uint32_t addr) {
    asm volatile("ldmatrix.sync.aligned.m8n8.x4.shared.b16 {%0,%1,%2,%3}, [%4];"
        : "=r"(r[0]), "=r"(r[1]), "=r"(r[2]), "=r"(r[3]) : "r"(addr));
}

__device__ __forceinline__ void mma16816(float* c, const uint32_t* a, const uint32_t* b) {
    asm volatile(
        "mma.sync.aligned.m16n8k16.row.col.f32.f16.f16.f32 "
        "{%0,%1,%2,%3}, {%4,%5,%6,%7}, {%8,%9}, {%0,%1,%2,%3};"
        : "+f"(c[0]), "+f"(c[1]), "+f"(c[2]), "+f"(c[3])
        : "r"(a[0]), "r"(a[1]), "r"(a[2]), "r"(a[3]), "r"(b[0]), "r"(b[1]));
}

// ======================= fp16 HMMA GEMM (bulk-copy fill) =======================
// C[M,N] = A[M,K] * B[N,K]^T, fp16 in, fp32 acc.
// CTA tile 128xBN, K chunks of 128, cp.async.bulk per tile-row (256B each),
// mbarrier-gated double buffer. 256 threads = 8 warps.
// BN=128: 2m x 4n warps (warp tile 64x32); BN=64: 4m x 2n (32x32).
// smem row stride 136 fp16 (272B, 16B-multiple) -> ldmatrix conflict-free.

#define GB_CHUNK 128
#define GB_STRIDE 136

// EPI: 0 = store, 2 = += resid
template <int EPI, int BN>
__global__ void __launch_bounds__(256, 1) gemm_hmma_kernel(
    int K,
    const __half* __restrict__ A, int lda,
    const __half* __restrict__ B, int ldb,
    float* __restrict__ C, int ldc,
    const float* __restrict__ resid) {
    extern __shared__ __half smem[];
    const uint32_t sbu = smem_to_u32(smem);
    const int tid = threadIdx.x;
    const int wid = tid >> 5, lane = tid & 31;
    const int bm0 = blockIdx.y * 128, bn0 = blockIdx.x * BN;

    constexpr int A_ELE = 128 * GB_STRIDE;
    constexpr int B_ELE = BN * GB_STRIDE;
    constexpr int BUF_ELE = A_ELE + B_ELE;
    constexpr int MT = (BN == 128) ? 4 : 2;
    constexpr int ROW_BYTES = GB_CHUNK * 2;             // 256B per row bulk

    const uint32_t mb0 = sbu, mb1 = sbu + 8;
    const uint32_t tiles = sbu + 32;

    const int wm = (BN == 128) ? (wid >> 2) * 64 : (wid >> 1) * 32;
    const int wn = (BN == 128) ? (wid & 3) * 32 : (wid & 1) * 32;

    // per-thread fill role: one tile-row per thread
    const int r = tid;
    const __half* gsrc_base = nullptr;
    uint32_t sdst_rel = 0;
    if (r < 128) {
        gsrc_base = A + (size_t)(bm0 + r) * lda;
        sdst_rel = (uint32_t)(r * GB_STRIDE) * 2;
    } else if (r < 128 + BN) {
        int rr = r - 128;
        gsrc_base = B + (size_t)(bn0 + rr) * ldb;
        sdst_rel = (uint32_t)(A_ELE + rr * GB_STRIDE) * 2;
    }

    auto fill = [&](int ck, int buf, uint32_t mbar) {
        if (gsrc_base) {
            MBARRIER_ARRIVE_EXPECT_TX(mbar, ROW_BYTES);
            uint32_t dst = tiles + (uint32_t)(buf * BUF_ELE) * 2 + sdst_rel;
            CP_BULK(dst, gsrc_base + ck * GB_CHUNK, ROW_BYTES, mbar);
        } else {
            MBARRIER_ARRIVE(mbar);
        }
    };

    if (tid == 0) { MBARRIER_INIT(mb0, 256); MBARRIER_INIT(mb1, 256); }
    __syncthreads();

    const int NC = K / GB_CHUNK;   // >= 2 for all callers
    fill(0, 0, mb0);
    fill(1, 1, mb1);

    float acc[MT][4][4];
    #pragma unroll
    for (int i = 0; i < MT; i++)
        #pragma unroll
        for (int j = 0; j < 4; j++)
            #pragma unroll
            for (int q = 0; q < 4; q++) acc[i][j][q] = 0.f;

    const int a_row = ((lane >> 3) & 1) * 8 + (lane & 7);
    const int a_col = ((lane >> 4) & 1) * 8;
    const int b_row = ((lane >> 4) & 1) * 8 + (lane & 7);
    const int b_col = ((lane >> 3) & 1) * 8;

    for (int ck = 0; ck < NC; ck++) {
        const int b = ck & 1;
        const uint32_t mbar = b ? mb1 : mb0;
        MBARRIER_WAIT_PARITY(mbar, (ck >> 1) & 1);

        const uint32_t sA = tiles + (uint32_t)(b * BUF_ELE) * 2;
        const uint32_t sB = sA + (uint32_t)A_ELE * 2;

        #pragma unroll
        for (int kk = 0; kk < GB_CHUNK / 16; kk++) {
            const int kc = kk * 16;
            uint32_t ah[MT][4], bh[4][2];
            #pragma unroll
            for (int mt = 0; mt < MT; mt++) {
                uint32_t off = (uint32_t)((wm + mt * 16 + a_row) * GB_STRIDE + kc + a_col) * 2;
                ldmatrix_x4(ah[mt], sA + off);
            }
            #pragma unroll
            for (int nt2 = 0; nt2 < 2; nt2++) {
                uint32_t off = (uint32_t)((wn + nt2 * 16 + b_row) * GB_STRIDE + kc + b_col) * 2;
                uint32_t rr[4];
                ldmatrix_x4(rr, sB + off);
                bh[nt2 * 2][0] = rr[0]; bh[nt2 * 2][1] = rr[1];
                bh[nt2 * 2 + 1][0] = rr[2]; bh[nt2 * 2 + 1][1] = rr[3];
            }
            #pragma unroll
            for (int mt = 0; mt < MT; mt++)
                #pragma unroll
                for (int nt = 0; nt < 4; nt++)
                    mma16816(acc[mt][nt], ah[mt], bh[nt]);
        }

        __syncthreads();                 // all warps done reading buffer b
        if (ck + 2 < NC) fill(ck + 2, b, mbar);
    }

    const int er = lane >> 2, ec = (lane & 3) * 2;
    #pragma unroll
    for (int mt = 0; mt < MT; mt++) {
        #pragma unroll
        for (int nt = 0; nt < 4; nt++) {
            int row = bm0 + wm + mt * 16 + er;
            int col = bn0 + wn + nt * 8 + ec;
            float2 v0 = make_float2(acc[mt][nt][0], acc[mt][nt][1]);
            float2 v1 = make_float2(acc[mt][nt][2], acc[mt][nt][3]);
            if (EPI == 2) {
                const float2 r0 = *reinterpret_cast<const float2*>(
                    resid + (size_t)row * ldc + col);
                const float2 r1 = *reinterpret_cast<const float2*>(
                    resid + (size_t)(row + 8) * ldc + col);
                v0.x += r0.x; v0.y += r0.y;
                v1.x += r1.x; v1.y += r1.y;
            }
            *reinterpret_cast<float2*>(C + (size_t)row * ldc + col) = v0;
            *reinterpret_cast<float2*>(C + (size_t)(row + 8) * ldc + col) = v1;
        }
    }
}

#define GB_SMEM(BN) (32 + 2 * (128 + (BN)) * GB_STRIDE * 2)
#define GB_SMEM_128 GB_SMEM(128)   // 139,296 B
#define GB_SMEM_64  GB_SMEM(64)    // 104,480 B

// ---------------- fused fp32 -> fp16 conversion of all weights ----------------
#define CVT_N1 (VOCAB * DMODEL)
#define CVT_N2 (NLAYER * 2 * DINNER * DMODEL)
#define CVT_N3 (NLAYER * DMODEL * DINNER)
__global__ void cvt_all_kernel(const float* __restrict__ emb,
                               const float* __restrict__ inw,
                               const float* __restrict__ ow,
                               __half* __restrict__ we16,
                               __half* __restrict__ wi16,
                               __half* __restrict__ wo16) {
    int i = (blockIdx.x * blockDim.x + threadIdx.x) * 4;
    const float* src;
    __half* dst;
    if (i < CVT_N1) {
        src = emb + i; dst = we16 + i;
    } else if (i < CVT_N1 + CVT_N2) {
        src = inw + (i - CVT_N1); dst = wi16 + (i - CVT_N1);
    } else if (i < CVT_N1 + CVT_N2 + CVT_N3) {
        src = ow + (i - CVT_N1 - CVT_N2); dst = wo16 + (i - CVT_N1 - CVT_N2);
    } else {
        return;
    }
    float4 v = *reinterpret_cast<const float4*>(src);
    *reinterpret_cast<__half2*>(dst)     = __floats2half2_rn(v.x, v.y);
    *reinterpret_cast<__half2*>(dst + 2) = __floats2half2_rn(v.z, v.w);
}

// ---------------- block reductions (loss only) ----------------
__device__ __forceinline__ float blockReduceSum(float v) {
    __shared__ float sh[9];
    int lane = threadIdx.x & 31, w = threadIdx.x >> 5;
    #pragma unroll
    for (int o = 16; o; o >>= 1) v += __shfl_xor_sync(0xffffffffu, v, o);
    if (lane == 0) sh[w] = v;
    __syncthreads();
    if (threadIdx.x == 0) {
        float s = 0.f;
        int nw = (blockDim.x + 31) >> 5;
        for (int i = 0; i < nw; i++) s += sh[i];
        sh[8] = s;
    }
    __syncthreads();
    float r = sh[8];
    __syncthreads();
    return r;
}

__device__ __forceinline__ float blockReduceMax(float v) {
    __shared__ float sh[9];
    int lane = threadIdx.x & 31, w = threadIdx.x >> 5;
    #pragma unroll
    for (int o = 16; o; o >>= 1) v = fmaxf(v, __shfl_xor_sync(0xffffffffu, v, o));
    if (lane == 0) sh[w] = v;
    __syncthreads();
    if (threadIdx.x == 0) {
        float s = -1e30f;
        int nw = (blockDim.x + 31) >> 5;
        for (int i = 0; i < nw; i++) s = fmaxf(s, sh[i]);
        sh[8] = s;
    }
    __syncthreads();
    float r = sh[8];
    __syncthreads();
    return r;
}

// ---------------- embedding ----------------
__global__ void embed_kernel(const int* __restrict__ ids,
                             const float* __restrict__ emb,
                             const float* __restrict__ pos) {
    int i = blockIdx.x * blockDim.x + threadIdx.x;
    if (i >= LSEQ * DMODEL) return;
    int t = i / DMODEL;
    int d = i - t * DMODEL;
    g_h[i] = emb[(size_t)ids[t] * DMODEL + d] + pos[i];
}

// ---------------- rmsnorm -> fp16, warp per token ----------------
__global__ void rmsnorm_kernel(const float* __restrict__ src,
                               const float* __restrict__ w,
                               __half* __restrict__ dst) {
    int warp = threadIdx.x >> 5, lane = threadIdx.x & 31;
    int t = blockIdx.x * 8 + warp;
    const float* r = src + (size_t)t * DMODEL;
    float4 v[4];
    float ss = 0.f;
    #pragma unroll
    for (int q = 0; q < 4; q++) {
        v[q] = *reinterpret_cast<const float4*>(r + (q * 32 + lane) * 4);
        ss += v[q].x * v[q].x + v[q].y * v[q].y + v[q].z * v[q].z + v[q].w * v[q].w;
    }
    #pragma unroll
    for (int o = 16; o; o >>= 1) ss += __shfl_xor_sync(0xffffffffu, ss, o);
    float sc = rsqrtf(ss * (1.0f / DMODEL) + 1e-6f);
    __half* dp = dst + (size_t)t * DMODEL;
    #pragma unroll
    for (int q = 0; q < 4; q++) {
        int idx = (q * 32 + lane) * 4;
        float4 w4 = *reinterpret_cast<const float4*>(w + idx);
        __half2 h0 = __floats2half2_rn(v[q].x * sc * w4.x, v[q].y * sc * w4.y);
        __half2 h1 = __floats2half2_rn(v[q].z * sc * w4.z, v[q].w * sc * w4.w);
        *reinterpret_cast<__half2*>(dp + idx)     = h0;
        *reinterpret_cast<__half2*>(dp + idx + 2) = h1;
    }
}

// =================================================================================
// fp32 GEMM 64x64x16 (small xproj/dt), double-buffered, 256 threads, 4x4/thread
// split-K via blockIdx.z.
// EPI: 0 = plain store, 1 = softplus(v+bias[col]) stored TRANSPOSED (C[col][row])
// SUMA: A elements are the sum of 4 split-K partials at stride LSEQ*XDIM
// =================================================================================
template <int EPI, int SUMA>
__global__ void __launch_bounds__(256) gemm64_kernel(
    int Kloc,
    const float* __restrict__ A, int lda,
    const float* __restrict__ B, int ldb,
    float* __restrict__ C, int ldc, int partStride,
    const float* __restrict__ bias) {
    __shared__ float As[2][16][68];
    __shared__ float Bs[2][16][68];
    const int tid = threadIdx.x;
    const int bm0 = blockIdx.y * 64, bn0 = blockIdx.x * 64;
    const int kbase = blockIdx.z * Kloc;
    C += (size_t)blockIdx.z * partStride;

    const int lrow = tid >> 2;
    const int kq0  = (tid & 3) << 2;
    const float* Ap = A + (size_t)(bm0 + lrow) * lda + kbase + kq0;
    const float* Bp = B + (size_t)(bn0 + lrow) * ldb + kbase + kq0;
    const int PS = LSEQ * XDIM;

    const int ty = tid >> 4, tx = tid & 15;

    float acc[4][4];
    #pragma unroll
    for (int i = 0; i < 4; i++)
        #pragma unroll
        for (int j = 0; j < 4; j++) acc[i][j] = 0.f;

    auto loadA = [&](int off) -> float4 {
        float4 a = *reinterpret_cast<const float4*>(Ap + off);
        if (SUMA) {
            float4 p1 = *reinterpret_cast<const float4*>(Ap + off + PS);
            float4 p2 = *reinterpret_cast<const float4*>(Ap + off + 2 * PS);
            float4 p3 = *reinterpret_cast<const float4*>(Ap + off + 3 * PS);
            a.x = a.x + p1.x + p2.x + p3.x;
            a.y = a.y + p1.y + p2.y + p3.y;
            a.z = a.z + p1.z + p2.z + p3.z;
            a.w = a.w + p1.w + p2.w + p3.w;
        }
        return a;
    };

    float4 av = loadA(0);
    float4 bv = *reinterpret_cast<const float4*>(Bp);
    As[0][kq0 + 0][lrow] = av.x; As[0][kq0 + 1][lrow] = av.y;
    As[0][kq0 + 2][lrow] = av.z; As[0][kq0 + 3][lrow] = av.w;
    Bs[0][kq0 + 0][lrow] = bv.x; Bs[0][kq0 + 1][lrow] = bv.y;
    Bs[0][kq0 + 2][lrow] = bv.z; Bs[0][kq0 + 3][lrow] = bv.w;
    __syncthreads();

    const int KT = Kloc >> 4;
    for (int kt = 0; kt < KT; kt++) {
        const int cur = kt & 1, nxt = cur ^ 1;
        if (kt + 1 < KT) {
            int off = (kt + 1) << 4;
            av = loadA(off);
            bv = *reinterpret_cast<const float4*>(Bp + off);
        }
        #pragma unroll
        for (int kk = 0; kk < 16; kk++) {
            float4 a4 = *reinterpret_cast<const float4*>(&As[cur][kk][ty * 4]);
            float4 b4 = *reinterpret_cast<const float4*>(&Bs[cur][kk][tx * 4]);
            float a[4] = {a4.x, a4.y, a4.z, a4.w};
            float b[4] = {b4.x, b4.y, b4.z, b4.w};
            #pragma unroll
            for (int i = 0; i < 4; i++)
                #pragma unroll
                for (int j = 0; j < 4; j++)
                    acc[i][j] = fmaf(a[i], b[j], acc[i][j]);
        }
        if (kt + 1 < KT) {
            As[nxt][kq0 + 0][lrow] = av.x; As[nxt][kq0 + 1][lrow] = av.y;
            As[nxt][kq0 + 2][lrow] = av.z; As[nxt][kq0 + 3][lrow] = av.w;
            Bs[nxt][kq0 + 0][lrow] = bv.x; Bs[nxt][kq0 + 1][lrow] = bv.y;
            Bs[nxt][kq0 + 2][lrow] = bv.z; Bs[nxt][kq0 + 3][lrow] = bv.w;
            __syncthreads();
        }
    }

    if (EPI == 1) {
        float4 bias4 = *reinterpret_cast<const float4*>(&bias[bn0 + tx * 4]);
        float bb[4] = {bias4.x, bias4.y, bias4.z, bias4.w};
        #pragma unroll
        for (int i = 0; i < 4; i++)
            #pragma unroll
            for (int j = 0; j < 4; j++) {
                float v = acc[i][j] + bb[j];
                acc[i][j] = (v > 20.f) ? v : log1pf(expf(v));
            }
        int row0 = bm0 + ty * 4;
        #pragma unroll
        for (int j = 0; j < 4; j++) {
            int col = bn0 + tx * 4 + j;
            float4 v = make_float4(acc[0][j], acc[1][j], acc[2][j], acc[3][j]);
            *reinterpret_cast<float4*>(C + (size_t)col * ldc + row0) = v;
        }
    } else {
        #pragma unroll
        for (int i = 0; i < 4; i++) {
            int row = bm0 + ty * 4 + i;
            float* cp = C + (size_t)row * ldc + bn0 + tx * 4;
            *reinterpret_cast<float4*>(cp) =
                make_float4(acc[i][0], acc[i][1], acc[i][2], acc[i][3]);
        }
    }
}

// ---------------- reduce the 4 split-K partials: bcT only ----------------
__global__ void reduce4_kernel() {
    int j = blockIdx.x * blockDim.x + threadIdx.x;
    const int NB = 2 * DSTATE * LSEQ;   // 65536
    const int PS = LSEQ * XDIM;
    if (j >= NB) return;
    int s2 = j >> 11, t = j & (LSEQ - 1);
    int b = t * XDIM + DTRANK + s2;
    g_bcT[j] = g_xpart[b] + g_xpart[b + PS] + g_xpart[b + 2 * PS] + g_xpart[b + 3 * PS];
}

// ---------------- depthwise causal conv (width 4) + bias + silu ----------------
__global__ void conv_silu_kernel(const float* __restrict__ cw,
                                 const float* __restrict__ cb) {
    __shared__ float su[64][33];
    const int c0 = blockIdx.x * 64;
    const int t0 = blockIdx.y * 32;
    const int tid = threadIdx.x;
    #pragma unroll
    for (int it = 0; it < 8; it++) {
        int idx = it * 256 + tid;
        int cl = idx & 63, tl = idx >> 6;
        int c = c0 + cl, t = t0 + tl;
        float v = cb[c];
        #pragma unroll
        for (int k = 0; k < DCONV; k++) {
            int tt = t - (DCONV - 1) + k;
            if (tt >= 0)
                v = fmaf(g_xz[(size_t)tt * (2 * DINNER) + c], cw[c * DCONV + k], v);
        }
        float s = v / (1.f + expf(-v));
        g_u[(size_t)t * DINNER + c] = s;
        su[cl][tl] = s;
    }
    __syncthreads();
    #pragma unroll
    for (int it = 0; it < 8; it++) {
        int cl = it * 8 + (tid >> 5);
        int tl = tid & 31;
        g_uT[(size_t)(c0 + cl) * LSEQ + (t0 + tl)] = su[cl][tl];
    }
}

// ---------------- selective scan (fused y-combine, emits fp16) ----------------
__global__ void scan_kernel(const float* __restrict__ deltaT,
                            const float* __restrict__ uT,
                            const float* __restrict__ bcT,
                            const float* __restrict__ A_log,
                            const float* __restrict__ xz,
                            const float* __restrict__ Dp,
                            __half* __restrict__ yout) {
    int warp = threadIdx.x >> 5;
    int lane = threadIdx.x & 31;
    int half = lane >> 4;
    int s    = lane & 15;
    int ch   = blockIdx.x * 8 + warp * 2 + half;

    float A2 = -__expf(A_log[ch * DSTATE + s]) * 1.44269504088896f;
    float dpv = Dp[ch];
    float h = 0.f;
    const float* dT  = deltaT + (size_t)ch * LSEQ;
    const float* uTp = uT + (size_t)ch * LSEQ;
    const float* bT  = bcT + (size_t)s * LSEQ;
    const float* cT  = bcT + (size_t)(DSTATE + s) * LSEQ;

    for (int t0 = 0; t0 < LSEQ; t0 += 16) {
        float dv[16], uv[16], bv[16], cv[16];
        #pragma unroll
        for (int q = 0; q < 4; q++) {
            float4 d4 = *reinterpret_cast<const float4*>(dT + t0 + q * 4);
            float4 u4 = *reinterpret_cast<const float4*>(uTp + t0 + q * 4);
            float4 b4 = *reinterpret_cast<const float4*>(bT + t0 + q * 4);
            float4 c4 = *reinterpret_cast<const float4*>(cT + t0 + q * 4);
            dv[q*4+0]=d4.x; dv[q*4+1]=d4.y; dv[q*4+2]=d4.z; dv[q*4+3]=d4.w;
            uv[q*4+0]=u4.x; uv[q*4+1]=u4.y; uv[q*4+2]=u4.z; uv[q*4+3]=u4.w;
            bv[q*4+0]=b4.x; bv[q*4+1]=b4.y; bv[q*4+2]=b4.z; bv[q*4+3]=b4.w;
            cv[q*4+0]=c4.x; cv[q*4+1]=c4.y; cv[q*4+2]=c4.z; cv[q*4+3]=c4.w;
        }
        float p[16];
        #pragma unroll
        for (int j = 0; j < 16; j++) {
            float dA  = exp2f(dv[j] * A2);
            float dbu = dv[j] * uv[j] * bv[j];
            h = fmaf(dA, h, dbu);
            p[j] = h * cv[j];
        }
        float out = 0.f, uo = 0.f;
        #pragma unroll
        for (int j = 0; j < 16; j++) {
            float v = p[j];
            v += __shfl_xor_sync(0xffffffffu, v, 1);
            v += __shfl_xor_sync(0xffffffffu, v, 2);
            v += __shfl_xor_sync(0xffffffffu, v, 4);
            v += __shfl_xor_sync(0xffffffffu, v, 8);
            if (s == j) { out = v; uo = uv[j]; }
        }
        int t = t0 + s;
        float zz = xz[(size_t)t * (2 * DINNER) + DINNER + ch];
        float sz = zz / (1.f + expf(-zz));
        yout[(size_t)t * DINNER + ch] = __float2half((out + uo * dpv) * sz);
    }
}

// ---------------- cross-entropy loss over logits ----------------
__global__ void loss_kernel(const int* __restrict__ labels,
                            const float* __restrict__ logits) {
    int t = blockIdx.x;
    const float* row = logits + (size_t)t * VOCAB;
    float mx = -1e30f;
    for (int j = threadIdx.x; j < VOCAB; j += 256) mx = fmaxf(mx, row[j]);
    mx = blockReduceMax(mx);
    float sum = 0.f;
    for (int j = threadIdx.x; j < VOCAB; j += 256) sum += expf(row[j] - mx);
    sum = blockReduceSum(sum);
    if (threadIdx.x == 0) {
        int tgt = labels[t + 1];
        if (tgt != -100) {
            float lp = row[tgt] - mx - logf(sum);
            atomicAdd(&g_loss[0], -lp);
            atomicAdd(&g_loss[1], 1.f);
        }
    }
}

__global__ void loss_final_kernel(float* __restrict__ out, int idx) {
    out[idx] = g_loss[0] / fmaxf(g_loss[1], 1.f);
}

// ---------------- driver ----------------
extern "C" void kernel_launch(void* const* d_in, const int* in_sizes, int n_in,
                              void* d_out, int out_size) {
    const int*   ids    = (const int*)  d_in[0];
    const int*   labels = (const int*)  d_in[1];
    const float* emb    = (const float*)d_in[2];
    const float* pos    = (const float*)d_in[3];
    const float* fnw    = (const float*)d_in[4];
    const float* nw     = (const float*)d_in[5];
    const float* inw    = (const float*)d_in[6];
    const float* cw     = (const float*)d_in[7];
    const float* cb     = (const float*)d_in[8];
    const float* xw     = (const float*)d_in[9];
    const float* dw     = (const float*)d_in[10];
    const float* db     = (const float*)d_in[11];
    const float* alog   = (const float*)d_in[12];
    const float* dp     = (const float*)d_in[13];
    const float* ow     = (const float*)d_in[14];
    float* out = (float*)d_out;

    float *ph, *pxz, *pu, *puT, *pxpart, *pbcT, *pdT, *ploss;
    __half *pa16, *pwe16, *pwi16, *pwo16;
    cudaGetSymbolAddress((void**)&ph,     g_h);
    cudaGetSymbolAddress((void**)&pxz,    g_xz);
    cudaGetSymbolAddress((void**)&pu,     g_u);
    cudaGetSymbolAddress((void**)&puT,    g_uT);
    cudaGetSymbolAddress((void**)&pxpart, g_xpart);
    cudaGetSymbolAddress((void**)&pbcT,   g_bcT);
    cudaGetSymbolAddress((void**)&pdT,    g_deltaT);
    cudaGetSymbolAddress((void**)&ploss,  g_loss);
    cudaGetSymbolAddress((void**)&pa16,   g_a16);
    cudaGetSymbolAddress((void**)&pwe16,  g_wemb16);
    cudaGetSymbolAddress((void**)&pwi16,  g_win16);
    cudaGetSymbolAddress((void**)&pwo16,  g_wout16);

    cudaFuncSetAttribute((const void*)gemm_hmma_kernel<0, 128>,
        cudaFuncAttributeMaxDynamicSharedMemorySize, GB_SMEM_128);
    cudaFuncSetAttribute((const void*)gemm_hmma_kernel<2, 64>,
        cudaFuncAttributeMaxDynamicSharedMemorySize, GB_SMEM_64);

    embed_kernel<<<(LSEQ * DMODEL + 255) / 256, 256>>>(ids, emb, pos);
    {
        int total = CVT_N1 + CVT_N2 + CVT_N3;
        cvt_all_kernel<<<(total / 4 + 255) / 256, 256>>>(
            emb, inw, ow, pwe16, pwi16, pwo16);
    }

    for (int l = 0; l < NLAYER; l++) {
        const float* nw_l  = nw   + (size_t)l * DMODEL;
        const float* cw_l  = cw   + (size_t)l * DINNER * DCONV;
        const float* cb_l  = cb   + (size_t)l * DINNER;
        const float* xw_l  = xw   + (size_t)l * XDIM * DINNER;
        const float* dw_l  = dw   + (size_t)l * DINNER * DTRANK;
        const float* db_l  = db   + (size_t)l * DINNER;
        const float* al_l  = alog + (size_t)l * DINNER * DSTATE;
        const float* dp_l  = dp   + (size_t)l * DINNER;
        const __half* wi_l = pwi16 + (size_t)l * 2 * DINNER * DMODEL;
        const __half* wo_l = pwo16 + (size_t)l * DMODEL * DINNER;

        // x = rmsnorm(h) -> fp16 (warp per token)
        rmsnorm_kernel<<<LSEQ / 8, 256>>>(ph, nw_l, pa16);
        // xz = x @ in_w^T  [2048 x 2048], K=512 (HMMA, bulk fill)
        gemm_hmma_kernel<0, 128>
            <<<dim3(2 * DINNER / 128, LSEQ / 128), 256, GB_SMEM_128>>>(
            DMODEL, pa16, DMODEL, wi_l, DMODEL, pxz, 2 * DINNER, nullptr);
        // u = silu(causal depthwise conv(xi) + b)  (u and u_T, both coalesced)
        conv_silu_kernel<<<dim3(DINNER / 64, LSEQ / 32), 256>>>(cw_l, cb_l);
        // xdbl partials = u @ xproj_w^T  [2048 x 64], K=1024, split-K x4 (fp32)
        gemm64_kernel<0, 0><<<dim3(1, LSEQ / 64, 4), 256>>>(
            DINNER / 4, pu, DINNER, xw_l, DINNER, pxpart, XDIM, LSEQ * XDIM, nullptr);
        // reduce bc partials -> bcT [32x2048]
        reduce4_kernel<<<(2 * DSTATE * LSEQ + 255) / 256, 256>>>();
        // delta_T = softplus((sum dt partials) @ dt_w^T + dt_b)^T  [1024 x 2048]
        gemm64_kernel<1, 1><<<dim3(DINNER / 64, LSEQ / 64), 256>>>(
            DTRANK, pxpart, XDIM, dw_l, DTRANK, pdT, LSEQ, 0, db_l);
        // selective scan + fused (y + u*Dp)*silu(z) -> fp16
        scan_kernel<<<DINNER / 8, 128>>>(pdT, puT, pbcT, al_l, pxz, dp_l, pa16);
        // h = h + yf @ out_w^T  [2048 x 512], K=1024 (HMMA, bulk fill)
        gemm_hmma_kernel<2, 64>
            <<<dim3(DMODEL / 64, LSEQ / 128), 256, GB_SMEM_64>>>(
            DINNER, pa16, DINNER, wo_l, DINNER, ph, DMODEL, ph);
    }

    // final norm + logits (HMMA, bulk fill)
    rmsnorm_kernel<<<LSEQ / 8, 256>>>(ph, fnw, pa16);
    gemm_hmma_kernel<0, 128>
        <<<dim3(VOCAB / 128, LSEQ / 128), 256, GB_SMEM_128>>>(
        DMODEL, pa16, DMODEL, pwe16, DMODEL, out, VOCAB, nullptr);

    // loss
    cudaMemsetAsync(ploss, 0, 2 * sizeof(float));
    loss_kernel<<<LSEQ - 1, 256>>>(labels, out);
    loss_final_kernel<<<1, 1>>>(out, out_size - 1);
}